// round 13
// baseline (speedup 1.0000x reference)
#include <cuda_runtime.h>

#define B_TOT   16
#define CIN     64
#define COUT    64
#define S_LEN   1024
#define KW      3
#define STILE   32
#define POSN    (STILE + 2)     // 34 input positions per tile (halo of 1 each side)
#define BH      8               // batches per block
#define OTILE   4               // outputs per thread
#define OGN     8               // o-groups per c-half
#define OBLK    (OGN * OTILE)   // 32 outputs per block
#define CHALF   (CIN / 2)       // 32 c per warp-half
#define NTHREADS 512            // 16 warps: [c-half][o-group]
#define SK      (S_LEN * KW)            // per-c weight stride (floats)
#define OCS     (CIN * S_LEN * KW)      // per-o weight stride (floats)
#define SMEM_FLOATS (CIN * BH * POSN)   // 64*8*34 = 17408 floats = 69632 B

__global__ void __launch_bounds__(NTHREADS)
locon1d_kernel(const float* __restrict__ X,     // (B, Cin, S)
               const float* __restrict__ W,     // (Cout, Cin, S, K)
               const float* __restrict__ Bias,  // (Cout, S)
               float* __restrict__ Out)         // (B, Cout, S)
{
    extern __shared__ float shx[];   // [c][b][pos] -> (c*BH + b)*POSN + pos

    const int s0     = blockIdx.x * STILE;
    const int o0base = blockIdx.y * OBLK;
    const int b0     = blockIdx.z * BH;
    const int tid    = threadIdx.x;
    const int sl     = tid & 31;          // lane = consecutive s
    const int wid    = tid >> 5;          // 0..15
    const int og     = wid & 7;           // o-group
    const int ch     = wid >> 3;          // c-half: 0 or 1

    // ── Input tile fill: warp -> (batch, c-half). No div/mod; coalesced rows.
    {
        const int  bf    = wid >> 1;                 // batch this warp fills
        const int  cbase = (wid & 1) * CHALF;        // 32 c-rows per warp
        const float* xb  = X + ((size_t)(b0 + bf) * CIN + cbase) * S_LEN;
        float*       shb = shx + ((size_t)cbase * BH + bf) * POSN;
        const int  sg    = s0 - 1 + sl;
        const bool m1    = (unsigned)sg < (unsigned)S_LEN;
        const int  sg2   = s0 + 31 + sl;
        const bool m2    = (sl < 2) && ((unsigned)sg2 < (unsigned)S_LEN);
        #pragma unroll 4
        for (int c = 0; c < CHALF; c++) {
            shb[(size_t)c * (BH * POSN) + sl] =
                m1 ? xb[(size_t)c * S_LEN + sg] : 0.0f;
            if (sl < 2)
                shb[(size_t)c * (BH * POSN) + 32 + sl] =
                    m2 ? xb[(size_t)c * S_LEN + sg2] : 0.0f;
        }
    }
    __syncthreads();

    const int s  = s0 + sl;
    const int o0 = o0base + og * OTILE;

    // acc[j][b]: 4 outputs x 8 batches = 32 registers.
    // c-half 0 starts from bias; c-half 1 starts from zero (partial sum).
    float acc[OTILE][BH];
    #pragma unroll
    for (int j = 0; j < OTILE; j++) {
        float bv = (ch == 0) ? Bias[(size_t)(o0 + j) * S_LEN + s] : 0.0f;
        #pragma unroll
        for (int b = 0; b < BH; b++) acc[j][b] = bv;
    }

    // ── Main loop: identical body to the 23.0us kernel; unroll 4 gives ptxas
    //    a deeper load-batching window (128-reg budget, still 1 block/SM).
    const float* wbase = W + (size_t)o0 * OCS
                           + (size_t)(ch * CHALF) * SK
                           + (size_t)s * KW;
    const float* xhalf = shx + (size_t)(ch * CHALF) * (BH * POSN) + sl;

    #pragma unroll 4
    for (int ci = 0; ci < CHALF; ci++) {
        float xr[BH][KW];
        const float* xc = xhalf + (size_t)ci * (BH * POSN);
        #pragma unroll
        for (int b = 0; b < BH; b++) {
            #pragma unroll
            for (int k = 0; k < KW; k++)
                xr[b][k] = xc[b * POSN + k];
        }

        const float* wc = wbase + (size_t)ci * SK;
        #pragma unroll
        for (int j = 0; j < OTILE; j++) {
            const float* wj = wc + (size_t)j * OCS;
            float w0 = wj[0];
            float w1 = wj[1];
            float w2 = wj[2];
            #pragma unroll
            for (int b = 0; b < BH; b++) {
                acc[j][b] += w0 * xr[b][0];
                acc[j][b] += w1 * xr[b][1];
                acc[j][b] += w2 * xr[b][2];
            }
        }
    }

    // ── Symmetric cross-half reduction: each half exchanges 2 j's and stores 2 j's.
    //    ch0 keeps j=0,1 (receives ch1's partials); ch1 keeps j=2,3 (receives
    //    ch0's bias-carrying partials). Both halves store 16 outputs each.
    __syncthreads();                        // mainloop reads of shx complete
    const int t2 = og * 32 + sl;            // 0..255 within a c-half
    {
        const int jsend = (ch == 0) ? 2 : 0;   // j-pair this half ships out
        #pragma unroll
        for (int jj = 0; jj < 2; jj++)
            #pragma unroll
            for (int b = 0; b < BH; b++)
                shx[((jsend + jj) * BH + b) * 256 + t2] = acc[jsend + jj][b];
    }
    __syncthreads();
    {
        const int jkeep = (ch == 0) ? 0 : 2;   // j-pair this half finalizes
        #pragma unroll
        for (int jj = 0; jj < 2; jj++) {
            const int j = jkeep + jj;
            #pragma unroll
            for (int b = 0; b < BH; b++) {
                float v = acc[j][b] + shx[(j * BH + b) * 256 + t2];
                // lanes = consecutive s -> fully coalesced 128B stores per warp.
                Out[((size_t)(b0 + b) * COUT + (o0 + j)) * S_LEN + s] = v;
            }
        }
    }
}

extern "C" void kernel_launch(void* const* d_in, const int* in_sizes, int n_in,
                              void* d_out, int out_size) {
    const float* x    = (const float*)d_in[0];
    const float* w    = (const float*)d_in[1];
    const float* bias = (const float*)d_in[2];
    float* out        = (float*)d_out;

    const int smem_bytes = SMEM_FLOATS * (int)sizeof(float);  // 69632 B > 48K -> opt-in
    cudaFuncSetAttribute(locon1d_kernel,
                         cudaFuncAttributeMaxDynamicSharedMemorySize, smem_bytes);

    dim3 grid(S_LEN / STILE, COUT / OBLK, B_TOT / BH);  // (32, 2, 2) = 128 blocks
    locon1d_kernel<<<grid, NTHREADS, smem_bytes>>>(x, w, bias, out);
}

// round 14
// speedup vs baseline: 1.6781x; 1.6781x over previous
#include <cuda_runtime.h>

#define B_TOT   16
#define CIN     64
#define COUT    64
#define S_LEN   1024
#define KW      3
#define STILE   32
#define POSN    (STILE + 2)     // 34 input positions per tile (halo of 1 each side)
#define BH      8               // batches per block
#define OTILE   4               // outputs per thread
#define OGN     8               // o-groups per c-half
#define OBLK    (OGN * OTILE)   // 32 outputs per block
#define CHALF   (CIN / 2)       // 32 c per warp-half
#define NTHREADS 512            // 16 warps: [c-half][o-group]
#define SK      (S_LEN * KW)            // per-c weight stride (floats)
#define OCS     (CIN * S_LEN * KW)      // per-o weight stride (floats)
#define PF      6                       // prefetch distance in c-iterations
#define SMEM_FLOATS (CIN * BH * POSN)   // 64*8*34 = 17408 floats = 69632 B

__global__ void __launch_bounds__(NTHREADS)
locon1d_kernel(const float* __restrict__ X,     // (B, Cin, S)
               const float* __restrict__ W,     // (Cout, Cin, S, K)
               const float* __restrict__ Bias,  // (Cout, S)
               float* __restrict__ Out)         // (B, Cout, S)
{
    extern __shared__ float shx[];   // [c][b][pos] -> (c*BH + b)*POSN + pos

    const int s0     = blockIdx.x * STILE;
    const int o0base = blockIdx.y * OBLK;
    const int b0     = blockIdx.z * BH;
    const int tid    = threadIdx.x;
    const int sl     = tid & 31;          // lane = consecutive s
    const int wid    = tid >> 5;          // 0..15
    const int og     = wid & 7;           // o-group
    const int ch     = wid >> 3;          // c-half: 0 or 1

    // ── Cooperative input tile fill (512 threads, coalesced along pos).
    for (int i = tid; i < SMEM_FLOATS; i += NTHREADS) {
        int pos = i % POSN;
        int bc  = i / POSN;
        int b   = bc % BH;
        int c   = bc / BH;
        int sg  = s0 - 1 + pos;
        float v = 0.0f;
        if ((unsigned)sg < (unsigned)S_LEN)
            v = X[((size_t)(b0 + b) * CIN + c) * S_LEN + sg];
        shx[i] = v;
    }
    __syncthreads();

    const int s  = s0 + sl;
    const int o0 = o0base + og * OTILE;

    // acc[j][b]: 4 outputs x 8 batches = 32 registers.
    // c-half 0 starts from bias; c-half 1 starts from zero (partial sum).
    float acc[OTILE][BH];
    #pragma unroll
    for (int j = 0; j < OTILE; j++) {
        float bv = (ch == 0) ? Bias[(size_t)(o0 + j) * S_LEN + s] : 0.0f;
        #pragma unroll
        for (int b = 0; b < BH; b++) acc[j][b] = bv;
    }

    // Weight base for (o0, c = ch*CHALF, s, k=0).
    const float* wbase = W + (size_t)o0 * OCS
                           + (size_t)(ch * CHALF) * SK
                           + (size_t)s * KW;
    const float* xhalf = shx + (size_t)(ch * CHALF) * (BH * POSN) + sl;

    // Warm the L2 pipeline for the first PF iterations (fire-and-forget).
    #pragma unroll
    for (int pi = 0; pi < PF; pi++) {
        const float* wp = wbase + (size_t)pi * SK;
        #pragma unroll
        for (int j = 0; j < OTILE; j++)
            asm volatile("prefetch.global.L2 [%0];" :: "l"(wp + (size_t)j * OCS));
    }

    #pragma unroll 2
    for (int ci = 0; ci < CHALF; ci++) {
        // L2-prefetch the weights PF iterations ahead. No dest reg, no
        // scoreboard -> cannot perturb the surrounding schedule.
        if (ci + PF < CHALF) {
            const float* wp = wbase + (size_t)(ci + PF) * SK;
            #pragma unroll
            for (int j = 0; j < OTILE; j++)
                asm volatile("prefetch.global.L2 [%0];" :: "l"(wp + (size_t)j * OCS));
        }

        // x window: 8 batches x 3 taps from shared (conflict-free: lanes are the
        // fastest smem dimension).
        float xr[BH][KW];
        const float* xc = xhalf + (size_t)ci * (BH * POSN);
        #pragma unroll
        for (int b = 0; b < BH; b++) {
            #pragma unroll
            for (int k = 0; k < KW; k++)
                xr[b][k] = xc[b * POSN + k];
        }

        const float* wc = wbase + (size_t)ci * SK;
        #pragma unroll
        for (int j = 0; j < OTILE; j++) {
            const float* wj = wc + (size_t)j * OCS;
            float w0 = wj[0];
            float w1 = wj[1];
            float w2 = wj[2];
            #pragma unroll
            for (int b = 0; b < BH; b++) {
                acc[j][b] += w0 * xr[b][0];
                acc[j][b] += w1 * xr[b][1];
                acc[j][b] += w2 * xr[b][2];
            }
        }
    }

    // ── Cross-half reduction through smem (reuse shx; x tile is dead now).
    //    Compile-time-constant acc indexing ONLY (dynamic indexing spills).
    __syncthreads();                       // all mainloop reads of shx done
    const int t2 = og * 32 + sl;           // 0..255 thread id within a half
    if (ch == 1) {
        #pragma unroll
        for (int j = 0; j < OTILE; j++)
            #pragma unroll
            for (int b = 0; b < BH; b++)
                shx[(j * BH + b) * 256 + t2] = acc[j][b];
    }
    __syncthreads();
    if (ch == 0) {
        #pragma unroll
        for (int j = 0; j < OTILE; j++) {
            #pragma unroll
            for (int b = 0; b < BH; b++) {
                float v = acc[j][b] + shx[(j * BH + b) * 256 + t2];
                // lanes = consecutive s -> fully coalesced 128B stores per warp.
                Out[((size_t)(b0 + b) * COUT + (o0 + j)) * S_LEN + s] = v;
            }
        }
    }
}

extern "C" void kernel_launch(void* const* d_in, const int* in_sizes, int n_in,
                              void* d_out, int out_size) {
    const float* x    = (const float*)d_in[0];
    const float* w    = (const float*)d_in[1];
    const float* bias = (const float*)d_in[2];
    float* out        = (float*)d_out;

    const int smem_bytes = SMEM_FLOATS * (int)sizeof(float);  // 69632 B > 48K -> opt-in
    cudaFuncSetAttribute(locon1d_kernel,
                         cudaFuncAttributeMaxDynamicSharedMemorySize, smem_bytes);

    dim3 grid(S_LEN / STILE, COUT / OBLK, B_TOT / BH);  // (32, 2, 2) = 128 blocks
    locon1d_kernel<<<grid, NTHREADS, smem_bytes>>>(x, w, bias, out);
}